// round 4
// baseline (speedup 1.0000x reference)
#include <cuda_runtime.h>
#include <math.h>
#include <stdint.h>

#define B_ 16
#define T_ 128
#define S_ 128
#define E_ 512
#define H_ 512
#define V_ 4096

#define LSTM_BLOCKS 128
#define LSTM_THREADS 512
#define LSTM_SMEM (512 * 20 * 4)   // h staged [512 k][20 stride] floats = 40KB

// ---------------- scratch (device globals; no cudaMalloc allowed) -------------
__device__ float g_x[2048 * 512];        // embedded input [B*T, E]
__device__ float g_gates[2048 * 2048];   // precomputed input gates [B*T, 4H]
__device__ float g_y1[2048 * 512];       // layer0 outputs
__device__ float g_cat[2048 * 1024];     // [y2 | context]  [B*T, H+E]
__device__ float g_encf[2048 * 512];     // enc_feat [B*S, H]
__device__ float g_decf[2048 * 512];     // dec_feat [B*T, H]
__device__ float g_ench_t[512 * 16];     // enc_hidden TRANSPOSED [k][b]
__device__ float g_h0[512 * 16];         // h double buffer A  [k][b]
__device__ float g_h1[512 * 16];         // h double buffer B  [k][b]
__device__ unsigned long long g_bar_cnt; // zero-initialized, monotone

// ---------------- fast activations ---------------------------------------------
__device__ __forceinline__ float fsig(float x)  { return 1.f / (1.f + __expf(-x)); }
__device__ __forceinline__ float ftanh(float x) { return 1.f - 2.f / (__expf(2.f * x) + 1.f); }

// ---------------- grid barrier (release/acquire, fence only on tid0) ----------
__device__ __forceinline__ void grid_barrier() {
    __syncthreads();
    if (threadIdx.x == 0) {
        unsigned long long old, cur;
        asm volatile("atom.add.release.gpu.u64 %0, [%1], 1;"
                     : "=l"(old) : "l"(&g_bar_cnt) : "memory");
        unsigned long long target = (old / LSTM_BLOCKS + 1ULL) * LSTM_BLOCKS;
        do {
            asm volatile("ld.acquire.gpu.u64 %0, [%1];"
                         : "=l"(cur) : "l"(&g_bar_cnt) : "memory");
            if (cur < target) __nanosleep(20);
        } while (cur < target);
    }
    __syncthreads();
}

// ---------------- embedding gather --------------------------------------------
__global__ void k_embed(const int* __restrict__ tgt, const float* __restrict__ emb,
                        float* __restrict__ x) {
    int r = blockIdx.x;
    int tok = tgt[r];
    ((float4*)x)[r * 128 + threadIdx.x] = ((const float4*)emb)[tok * 128 + threadIdx.x];
}

// ---------------- mean over source positions (writes TRANSPOSED [e][b]) -------
__global__ void k_mean(const float* __restrict__ mem, float* __restrict__ out_t) {
    int b = blockIdx.x;
    int e = threadIdx.x;
    float s = 0.f;
    for (int t = 0; t < S_; t++) s += mem[(b * S_ + t) * 512 + e];
    out_t[e * 16 + b] = s * (1.f / (float)S_);
}

// ---------------- tf32 tensor-core GEMM ----------------------------------------
__device__ __forceinline__ uint32_t f2tf32(float f) {
    uint32_t u; asm("cvt.rna.tf32.f32 %0, %1;" : "=r"(u) : "f"(f)); return u;
}
__device__ __forceinline__ void mma_tf32(float* d, const uint32_t* a, const uint32_t* b) {
    asm volatile("mma.sync.aligned.m16n8k8.row.col.f32.tf32.tf32.f32 "
        "{%0,%1,%2,%3}, {%4,%5,%6,%7}, {%8,%9}, {%0,%1,%2,%3};"
        : "+f"(d[0]), "+f"(d[1]), "+f"(d[2]), "+f"(d[3])
        : "r"(a[0]), "r"(a[1]), "r"(a[2]), "r"(a[3]), "r"(b[0]), "r"(b[1]));
}
__device__ __forceinline__ void sts_cvt4(float* dst, float4 v) {
    uint4 u;
    u.x = f2tf32(v.x); u.y = f2tf32(v.y); u.z = f2tf32(v.z); u.w = f2tf32(v.w);
    *(uint4*)dst = u;
}

__global__ __launch_bounds__(256, 2) void gemm_tf32(
    const float* __restrict__ A, int lda,
    const float* __restrict__ W, int ldw, int K,
    const float* __restrict__ bias1, const float* __restrict__ bias2,
    float* __restrict__ C, int ldc) {
    __shared__ float As[128 * 20];
    __shared__ float Bs[128 * 20];
    const int tid = threadIdx.x;
    const int m0 = blockIdx.y * 128, n0 = blockIdx.x * 128;
    const int warp = tid >> 5, lane = tid & 31;
    const int wm = (warp & 1) * 64;
    const int wn = (warp >> 1) * 32;
    const int g = lane >> 2, c = lane & 3;

    const int lr = tid >> 2;
    const int lq = tid & 3;
    const float* Ap = A + (size_t)(m0 + lr) * lda + lq * 4;
    const float* Wp = W + (size_t)(n0 + lr) * ldw + lq * 4;
    const size_t astep = (size_t)64 * lda;
    const size_t wstep = (size_t)64 * ldw;

    float4 ar0 = *(const float4*)(Ap);
    float4 ar1 = *(const float4*)(Ap + astep);
    float4 br0 = *(const float4*)(Wp);
    float4 br1 = *(const float4*)(Wp + wstep);

    float acc[4][4][4];
#pragma unroll
    for (int i = 0; i < 4; i++)
#pragma unroll
        for (int j = 0; j < 4; j++)
#pragma unroll
            for (int q = 0; q < 4; q++) acc[i][j][q] = 0.f;

    const int nkt = K >> 4;
    for (int kt = 0; kt < nkt; kt++) {
        __syncthreads();
        sts_cvt4(&As[lr * 20 + lq * 4], ar0);
        sts_cvt4(&As[(lr + 64) * 20 + lq * 4], ar1);
        sts_cvt4(&Bs[lr * 20 + lq * 4], br0);
        sts_cvt4(&Bs[(lr + 64) * 20 + lq * 4], br1);
        __syncthreads();
        if (kt + 1 < nkt) {
            const float* Ap2 = Ap + (kt + 1) * 16;
            const float* Wp2 = Wp + (kt + 1) * 16;
            ar0 = *(const float4*)(Ap2);
            ar1 = *(const float4*)(Ap2 + astep);
            br0 = *(const float4*)(Wp2);
            br1 = *(const float4*)(Wp2 + wstep);
        }
#pragma unroll
        for (int kk = 0; kk < 16; kk += 8) {
            uint32_t af[4][4];
            uint32_t bf[4][2];
#pragma unroll
            for (int mt = 0; mt < 4; mt++) {
                int mr = wm + mt * 16 + g;
                af[mt][0] = __float_as_uint(As[mr * 20 + kk + c]);
                af[mt][1] = __float_as_uint(As[(mr + 8) * 20 + kk + c]);
                af[mt][2] = __float_as_uint(As[mr * 20 + kk + c + 4]);
                af[mt][3] = __float_as_uint(As[(mr + 8) * 20 + kk + c + 4]);
            }
#pragma unroll
            for (int nt = 0; nt < 4; nt++) {
                int nr = wn + nt * 8 + g;
                bf[nt][0] = __float_as_uint(Bs[nr * 20 + kk + c]);
                bf[nt][1] = __float_as_uint(Bs[nr * 20 + kk + c + 4]);
            }
#pragma unroll
            for (int mt = 0; mt < 4; mt++)
#pragma unroll
                for (int nt = 0; nt < 4; nt++)
                    mma_tf32(acc[mt][nt], af[mt], bf[nt]);
        }
    }

    float bv0[4], bv1[4];
#pragma unroll
    for (int nt = 0; nt < 4; nt++) {
        int col = n0 + wn + nt * 8 + 2 * c;
        float x0 = bias1 ? __ldg(&bias1[col]) : 0.f;
        float x1 = bias1 ? __ldg(&bias1[col + 1]) : 0.f;
        if (bias2) { x0 += __ldg(&bias2[col]); x1 += __ldg(&bias2[col + 1]); }
        bv0[nt] = x0; bv1[nt] = x1;
    }
#pragma unroll
    for (int mt = 0; mt < 4; mt++) {
        int r0 = m0 + wm + mt * 16 + g;
#pragma unroll
        for (int nt = 0; nt < 4; nt++) {
            int col = n0 + wn + nt * 8 + 2 * c;
            float2 o0 = make_float2(acc[mt][nt][0] + bv0[nt], acc[mt][nt][1] + bv1[nt]);
            float2 o1 = make_float2(acc[mt][nt][2] + bv0[nt], acc[mt][nt][3] + bv1[nt]);
            *(float2*)&C[(size_t)r0 * ldc + col] = o0;
            *(float2*)&C[(size_t)(r0 + 8) * ldc + col] = o1;
        }
    }
}

// ---------------- persistent LSTM layer (f32x2 + in-warp reduce) ---------------
// 128 CTAs x 512 threads = 16 warps. Warp (hl, bg): computes all 4 gates of
// h index kh = bidx*4+hl for batches bg*4..bg*4+3. Lane = k-slice (k = lane+32i).
// Weights in registers; packed f32x2 FMAs (2 batches/inst); shfl butterfly
// reduce; cell update inline in lanes 0..3. h exchanged via global [k][b].
__global__ __launch_bounds__(LSTM_THREADS, 1) void k_lstm(
    const float* __restrict__ gates_pre,  // [B*T, 2048]
    const float* __restrict__ Whh,        // [2048, 512]
    const float* __restrict__ h_init_t,   // [512][16] transposed
    float* __restrict__ ybase, int ystride,
    float* __restrict__ hfin, float* __restrict__ cfin,
    float* __restrict__ hb0, float* __restrict__ hb1) {
    extern __shared__ float hs[];         // [512][20]

    const int tid = threadIdx.x;
    const int bidx = blockIdx.x;
    const int wid = tid >> 5, lane = tid & 31;
    const int hl = wid & 3, bg = wid >> 2;
    const int kh = bidx * 4 + hl;
    const int j = lane & 3;
    const int bb = bg * 4 + j;            // batch handled by cell lanes
    const bool cell_lane = (lane < 4);

    // weights: w[g][i] = Whh[g*512 + kh][lane + 32*i]
    float w[4][16];
#pragma unroll
    for (int g = 0; g < 4; g++) {
        const float* wr = Whh + (size_t)(g * 512 + kh) * 512 + lane;
#pragma unroll
        for (int i = 0; i < 16; i++) w[g][i] = __ldg(wr + 32 * i);
    }

    float c_reg = 0.f;
    grid_barrier();

    for (int t = 0; t < T_; t++) {
        const float* hin = (t == 0) ? h_init_t : ((t & 1) ? hb1 : hb0);
        float* hout      = (t & 1) ? hb0 : hb1;

        // stage h: thread tid owns k=tid, 16 floats -> stride-20 smem row
        {
            const float4* src = ((const float4*)hin) + tid * 4;
            float4 v0 = __ldcg(src + 0);
            float4 v1 = __ldcg(src + 1);
            float4 v2 = __ldcg(src + 2);
            float4 v3 = __ldcg(src + 3);
            float* dst = hs + tid * 20;
            *(float4*)(dst + 0)  = v0;
            *(float4*)(dst + 4)  = v1;
            *(float4*)(dst + 8)  = v2;
            *(float4*)(dst + 12) = v3;
        }
        __syncthreads();

        // input-gate preload (cell lanes only), latency hidden by dot loop
        float gp0 = 0.f, gp1 = 0.f, gp2 = 0.f, gp3 = 0.f;
        if (cell_lane) {
            const float* gpr = gates_pre + ((size_t)(bb * T_ + t)) * 2048 + kh;
            gp0 = __ldg(gpr);
            gp1 = __ldg(gpr + 512);
            gp2 = __ldg(gpr + 1024);
            gp3 = __ldg(gpr + 1536);
        }

        // dot: k = lane + 32*i; 4 gates x 4 batches via packed f32x2
        unsigned long long acc[4][2];
#pragma unroll
        for (int g = 0; g < 4; g++) { acc[g][0] = 0ULL; acc[g][1] = 0ULL; }
#pragma unroll
        for (int i = 0; i < 16; i++) {
            const float* hp = hs + (lane + 32 * i) * 20 + bg * 4;
            float4 h4 = *(const float4*)hp;
            unsigned long long h01, h23;
            asm("mov.b64 %0, {%1,%2};" : "=l"(h01) : "f"(h4.x), "f"(h4.y));
            asm("mov.b64 %0, {%1,%2};" : "=l"(h23) : "f"(h4.z), "f"(h4.w));
#pragma unroll
            for (int g = 0; g < 4; g++) {
                unsigned long long wp;
                asm("mov.b64 %0, {%1,%1};" : "=l"(wp) : "f"(w[g][i]));
                asm("fma.rn.f32x2 %0, %1, %2, %0;" : "+l"(acc[g][0]) : "l"(wp), "l"(h01));
                asm("fma.rn.f32x2 %0, %1, %2, %0;" : "+l"(acc[g][1]) : "l"(wp), "l"(h23));
            }
        }

        // butterfly reduce across 32 lanes (8 float2 values)
        float2 r[8];
#pragma unroll
        for (int g = 0; g < 4; g++) {
#pragma unroll
            for (int q = 0; q < 2; q++) {
                float lo, hi;
                asm("mov.b64 {%0,%1}, %2;" : "=f"(lo), "=f"(hi) : "l"(acc[g][q]));
                r[g * 2 + q] = make_float2(lo, hi);
            }
        }
#pragma unroll
        for (int off = 16; off; off >>= 1) {
#pragma unroll
            for (int q = 0; q < 8; q++) {
                r[q].x += __shfl_xor_sync(0xffffffffu, r[q].x, off);
                r[q].y += __shfl_xor_sync(0xffffffffu, r[q].y, off);
            }
        }

        // cell update in lanes 0..3 (lane j = batch bg*4+j)
        if (cell_lane) {
            // gate g, batch j: pair0=(b0,b1), pair1=(b2,b3)
            float s01_i = (j & 1) ? r[0].y : r[0].x;
            float s23_i = (j & 1) ? r[1].y : r[1].x;
            float gi = ((j & 2) ? s23_i : s01_i) + gp0;
            float s01_f = (j & 1) ? r[2].y : r[2].x;
            float s23_f = (j & 1) ? r[3].y : r[3].x;
            float gf = ((j & 2) ? s23_f : s01_f) + gp1;
            float s01_g = (j & 1) ? r[4].y : r[4].x;
            float s23_g = (j & 1) ? r[5].y : r[5].x;
            float gg = ((j & 2) ? s23_g : s01_g) + gp2;
            float s01_o = (j & 1) ? r[6].y : r[6].x;
            float s23_o = (j & 1) ? r[7].y : r[7].x;
            float go = ((j & 2) ? s23_o : s01_o) + gp3;

            float iv = fsig(gi);
            float fv = fsig(gf);
            float gv = ftanh(gg);
            float ov = fsig(go);
            c_reg = fv * c_reg + iv * gv;
            float hv = ov * ftanh(c_reg);
            hout[kh * 16 + bb] = hv;
            ybase[((size_t)(bb * T_ + t)) * ystride + kh] = hv;
            if (t == T_ - 1) {
                hfin[bb * 512 + kh] = hv;
                cfin[bb * 512 + kh] = c_reg;
            }
        }
        grid_barrier();
    }
}

// ---------------- fused attention: energy + softmax + context -----------------
__global__ __launch_bounds__(256) void k_attn(
    const float* __restrict__ encf, const float* __restrict__ decf,
    const float* __restrict__ mem, const unsigned char* __restrict__ mask,
    const float* __restrict__ v, const float* __restrict__ vb,
    float* __restrict__ outcat) {
    __shared__ float df[8][512];
    __shared__ float vsh[512];
    __shared__ float row[512];
    __shared__ float en[8][128];
    const int b = blockIdx.x;
    const int t0 = blockIdx.y * 8;
    const int tid = threadIdx.x;
    const int w = tid >> 5, lane = tid & 31;

    for (int i = tid; i < 512; i += 256) vsh[i] = v[i];
    for (int i = tid; i < 8 * 512; i += 256) {
        int jj = i >> 9, h = i & 511;
        df[jj][h] = decf[((size_t)(b * T_ + t0 + jj)) * 512 + h];
    }
    __syncthreads();
    const float vbv = vb[0];

    for (int s = 0; s < S_; s++) {
        for (int i = tid; i < 512; i += 256) row[i] = encf[((size_t)(b * S_ + s)) * 512 + i];
        __syncthreads();
        float e = 0.f;
#pragma unroll
        for (int i = 0; i < 16; i++) {
            int h = lane + 32 * i;
            e = fmaf(vsh[h], ftanh(row[h] + df[w][h]), e);
        }
#pragma unroll
        for (int off = 16; off; off >>= 1) e += __shfl_xor_sync(0xffffffffu, e, off);
        if (lane == 0) {
            e += vbv;
            if (mask[b * S_ + s]) e = -1e9f;
            en[w][s] = e;
        }
        __syncthreads();
    }

    {
        float vals[4];
        float m = -1e30f;
#pragma unroll
        for (int i = 0; i < 4; i++) { vals[i] = en[w][lane + 32 * i]; m = fmaxf(m, vals[i]); }
#pragma unroll
        for (int off = 16; off; off >>= 1) m = fmaxf(m, __shfl_xor_sync(0xffffffffu, m, off));
        float ssum = 0.f;
#pragma unroll
        for (int i = 0; i < 4; i++) { vals[i] = __expf(vals[i] - m); ssum += vals[i]; }
#pragma unroll
        for (int off = 16; off; off >>= 1) ssum += __shfl_xor_sync(0xffffffffu, ssum, off);
        float inv = 1.f / ssum;
#pragma unroll
        for (int i = 0; i < 4; i++) en[w][lane + 32 * i] = vals[i] * inv;
    }
    __syncthreads();

    float c0[8], c1[8];
#pragma unroll
    for (int jj = 0; jj < 8; jj++) { c0[jj] = 0.f; c1[jj] = 0.f; }
    for (int s = 0; s < S_; s++) {
        for (int i = tid; i < 512; i += 256) row[i] = mem[((size_t)(b * S_ + s)) * 512 + i];
        __syncthreads();
        float m0 = row[tid], m1 = row[tid + 256];
#pragma unroll
        for (int jj = 0; jj < 8; jj++) {
            float a = en[jj][s];
            c0[jj] = fmaf(a, m0, c0[jj]);
            c1[jj] = fmaf(a, m1, c1[jj]);
        }
        __syncthreads();
    }
#pragma unroll
    for (int jj = 0; jj < 8; jj++) {
        size_t rr = ((size_t)(b * T_ + t0 + jj)) * 1024 + 512;
        outcat[rr + tid] = c0[jj];
        outcat[rr + tid + 256] = c1[jj];
    }
}

// ---------------- launch -------------------------------------------------------
extern "C" void kernel_launch(void* const* d_in, const int* in_sizes, int n_in,
                              void* d_out, int out_size) {
    (void)in_sizes; (void)n_in; (void)out_size;
    const int*   tgt  = (const int*)d_in[0];
    const float* mem  = (const float*)d_in[1];
    const unsigned char* mask = (const unsigned char*)d_in[2];
    const float* emb  = (const float*)d_in[3];
    const float* Wih0 = (const float*)d_in[4];
    const float* Whh0 = (const float*)d_in[5];
    const float* bih0 = (const float*)d_in[6];
    const float* bhh0 = (const float*)d_in[7];
    const float* Wih1 = (const float*)d_in[8];
    const float* Whh1 = (const float*)d_in[9];
    const float* bih1 = (const float*)d_in[10];
    const float* bhh1 = (const float*)d_in[11];
    const float* Wh   = (const float*)d_in[12];
    const float* bh   = (const float*)d_in[13];
    const float* Ws   = (const float*)d_in[14];
    const float* bs   = (const float*)d_in[15];
    const float* v    = (const float*)d_in[16];
    const float* vb   = (const float*)d_in[17];
    const float* Wout = (const float*)d_in[18];
    const float* bout = (const float*)d_in[19];

    float* out = (float*)d_out;
    float* logits = out;
    float* hn = out + (size_t)B_ * T_ * V_;
    float* cn = hn + 2 * B_ * H_;

    float *px, *pgates, *py1, *pcat, *pencf, *pdecf, *pench, *ph0, *ph1;
    cudaGetSymbolAddress((void**)&px, g_x);
    cudaGetSymbolAddress((void**)&pgates, g_gates);
    cudaGetSymbolAddress((void**)&py1, g_y1);
    cudaGetSymbolAddress((void**)&pcat, g_cat);
    cudaGetSymbolAddress((void**)&pencf, g_encf);
    cudaGetSymbolAddress((void**)&pdecf, g_decf);
    cudaGetSymbolAddress((void**)&pench, g_ench_t);
    cudaGetSymbolAddress((void**)&ph0, g_h0);
    cudaGetSymbolAddress((void**)&ph1, g_h1);

    cudaFuncSetAttribute(k_lstm, cudaFuncAttributeMaxDynamicSharedMemorySize, LSTM_SMEM);

    // 1. embedding + enc_hidden (transposed)
    k_embed<<<2048, 128>>>(tgt, emb, px);
    k_mean<<<B_, 512>>>(mem, pench);

    // 2. layer0 input gates (tf32 mma), layer0 recurrence
    gemm_tf32<<<dim3(16, 16), 256>>>(px, 512, Wih0, 512, 512, bih0, bhh0, pgates, 2048);
    k_lstm<<<LSTM_BLOCKS, LSTM_THREADS, LSTM_SMEM>>>(pgates, Whh0, pench, py1, 512,
                                                     hn, cn, ph0, ph1);

    // 3. layer1 input gates, layer1 recurrence (y2 -> first half of g_cat)
    gemm_tf32<<<dim3(16, 16), 256>>>(py1, 512, Wih1, 512, 512, bih1, bhh1, pgates, 2048);
    k_lstm<<<LSTM_BLOCKS, LSTM_THREADS, LSTM_SMEM>>>(pgates, Whh1, pench, pcat, 1024,
                                                     hn + B_ * H_, cn + B_ * H_, ph0, ph1);

    // 4. attention features
    gemm_tf32<<<dim3(4, 16), 256>>>(mem, 512, Wh, 512, 512, bh, nullptr, pencf, 512);
    gemm_tf32<<<dim3(4, 16), 256>>>(pcat, 1024, Ws, 512, 512, bs, nullptr, pdecf, 512);

    // 5. fused energy/softmax/context -> second half of g_cat
    k_attn<<<dim3(B_, T_ / 8), 256>>>(pencf, pdecf, mem, mask, v, vb, pcat);

    // 6. output projection (tf32 mma)
    gemm_tf32<<<dim3(32, 16), 256>>>(pcat, 1024, Wout, 1024, 1024, bout, nullptr, logits, 4096);
}

// round 5
// speedup vs baseline: 1.2374x; 1.2374x over previous
#include <cuda_runtime.h>
#include <math.h>
#include <stdint.h>

#define B_ 16
#define T_ 128
#define S_ 128
#define E_ 512
#define H_ 512
#define V_ 4096

#define LSTM_BLOCKS 128
#define LSTM_THREADS 256

// ---------------- scratch (device globals; no cudaMalloc allowed) -------------
__device__ float g_x[2048 * 512];        // embedded input [B*T, E]
__device__ float g_gates[2048 * 2048];   // precomputed input gates [B*T, 4H]
__device__ float g_y1[2048 * 512];       // layer0 outputs
__device__ float g_cat[2048 * 1024];     // [y2 | context]  [B*T, H+E]
__device__ float g_encf[2048 * 512];     // enc_feat [B*S, H]
__device__ float g_decf[2048 * 512];     // dec_feat [B*T, H]
__device__ float g_ench_t[512 * 16];     // enc_hidden TRANSPOSED [k][b]
__device__ float g_h0[512 * 16];         // h double buffer A  [k][b]
__device__ float g_h1[512 * 16];         // h double buffer B  [k][b]
__device__ unsigned long long g_bar_cnt; // zero-initialized, monotone

// ---------------- fast activations ---------------------------------------------
__device__ __forceinline__ float fsig(float x)  { return 1.f / (1.f + __expf(-x)); }
__device__ __forceinline__ float ftanh(float x) { return 1.f - 2.f / (__expf(2.f * x) + 1.f); }

// ---------------- grid barrier (release/acquire, fence only on tid0) ----------
__device__ __forceinline__ void grid_barrier() {
    __syncthreads();
    if (threadIdx.x == 0) {
        unsigned long long old, cur;
        asm volatile("atom.add.release.gpu.u64 %0, [%1], 1;"
                     : "=l"(old) : "l"(&g_bar_cnt) : "memory");
        unsigned long long target = (old / LSTM_BLOCKS + 1ULL) * LSTM_BLOCKS;
        do {
            asm volatile("ld.acquire.gpu.u64 %0, [%1];"
                         : "=l"(cur) : "l"(&g_bar_cnt) : "memory");
            if (cur < target) __nanosleep(20);
        } while (cur < target);
    }
    __syncthreads();
}

// ---------------- embedding gather --------------------------------------------
__global__ void k_embed(const int* __restrict__ tgt, const float* __restrict__ emb,
                        float* __restrict__ x) {
    int r = blockIdx.x;
    int tok = tgt[r];
    ((float4*)x)[r * 128 + threadIdx.x] = ((const float4*)emb)[tok * 128 + threadIdx.x];
}

// ---------------- mean over source positions (writes TRANSPOSED [e][b]) -------
__global__ void k_mean(const float* __restrict__ mem, float* __restrict__ out_t) {
    int b = blockIdx.x;
    int e = threadIdx.x;
    float s = 0.f;
    for (int t = 0; t < S_; t++) s += mem[(b * S_ + t) * 512 + e];
    out_t[e * 16 + b] = s * (1.f / (float)S_);
}

// ---------------- tf32 helpers --------------------------------------------------
__device__ __forceinline__ uint32_t f2tf32(float f) {
    uint32_t u; asm("cvt.rna.tf32.f32 %0, %1;" : "=r"(u) : "f"(f)); return u;
}
__device__ __forceinline__ void mma_tf32(float* d, const uint32_t* a, const uint32_t* b) {
    asm volatile("mma.sync.aligned.m16n8k8.row.col.f32.tf32.tf32.f32 "
        "{%0,%1,%2,%3}, {%4,%5,%6,%7}, {%8,%9}, {%0,%1,%2,%3};"
        : "+f"(d[0]), "+f"(d[1]), "+f"(d[2]), "+f"(d[3])
        : "r"(a[0]), "r"(a[1]), "r"(a[2]), "r"(a[3]), "r"(b[0]), "r"(b[1]));
}
__device__ __forceinline__ void sts_cvt4(float* dst, float4 v) {
    uint4 u;
    u.x = f2tf32(v.x); u.y = f2tf32(v.y); u.z = f2tf32(v.z); u.w = f2tf32(v.w);
    *(uint4*)dst = u;
}

// ---------------- tf32 tensor-core GEMM ----------------------------------------
__global__ __launch_bounds__(256, 2) void gemm_tf32(
    const float* __restrict__ A, int lda,
    const float* __restrict__ W, int ldw, int K,
    const float* __restrict__ bias1, const float* __restrict__ bias2,
    float* __restrict__ C, int ldc) {
    __shared__ float As[128 * 20];
    __shared__ float Bs[128 * 20];
    const int tid = threadIdx.x;
    const int m0 = blockIdx.y * 128, n0 = blockIdx.x * 128;
    const int warp = tid >> 5, lane = tid & 31;
    const int wm = (warp & 1) * 64;
    const int wn = (warp >> 1) * 32;
    const int g = lane >> 2, c = lane & 3;

    const int lr = tid >> 2;
    const int lq = tid & 3;
    const float* Ap = A + (size_t)(m0 + lr) * lda + lq * 4;
    const float* Wp = W + (size_t)(n0 + lr) * ldw + lq * 4;
    const size_t astep = (size_t)64 * lda;
    const size_t wstep = (size_t)64 * ldw;

    float4 ar0 = *(const float4*)(Ap);
    float4 ar1 = *(const float4*)(Ap + astep);
    float4 br0 = *(const float4*)(Wp);
    float4 br1 = *(const float4*)(Wp + wstep);

    float acc[4][4][4];
#pragma unroll
    for (int i = 0; i < 4; i++)
#pragma unroll
        for (int j = 0; j < 4; j++)
#pragma unroll
            for (int q = 0; q < 4; q++) acc[i][j][q] = 0.f;

    const int nkt = K >> 4;
    for (int kt = 0; kt < nkt; kt++) {
        __syncthreads();
        sts_cvt4(&As[lr * 20 + lq * 4], ar0);
        sts_cvt4(&As[(lr + 64) * 20 + lq * 4], ar1);
        sts_cvt4(&Bs[lr * 20 + lq * 4], br0);
        sts_cvt4(&Bs[(lr + 64) * 20 + lq * 4], br1);
        __syncthreads();
        if (kt + 1 < nkt) {
            const float* Ap2 = Ap + (kt + 1) * 16;
            const float* Wp2 = Wp + (kt + 1) * 16;
            ar0 = *(const float4*)(Ap2);
            ar1 = *(const float4*)(Ap2 + astep);
            br0 = *(const float4*)(Wp2);
            br1 = *(const float4*)(Wp2 + wstep);
        }
#pragma unroll
        for (int kk = 0; kk < 16; kk += 8) {
            uint32_t af[4][4];
            uint32_t bf[4][2];
#pragma unroll
            for (int mt = 0; mt < 4; mt++) {
                int mr = wm + mt * 16 + g;
                af[mt][0] = __float_as_uint(As[mr * 20 + kk + c]);
                af[mt][1] = __float_as_uint(As[(mr + 8) * 20 + kk + c]);
                af[mt][2] = __float_as_uint(As[mr * 20 + kk + c + 4]);
                af[mt][3] = __float_as_uint(As[(mr + 8) * 20 + kk + c + 4]);
            }
#pragma unroll
            for (int nt = 0; nt < 4; nt++) {
                int nr = wn + nt * 8 + g;
                bf[nt][0] = __float_as_uint(Bs[nr * 20 + kk + c]);
                bf[nt][1] = __float_as_uint(Bs[nr * 20 + kk + c + 4]);
            }
#pragma unroll
            for (int mt = 0; mt < 4; mt++)
#pragma unroll
                for (int nt = 0; nt < 4; nt++)
                    mma_tf32(acc[mt][nt], af[mt], bf[nt]);
        }
    }

    float bv0[4], bv1[4];
#pragma unroll
    for (int nt = 0; nt < 4; nt++) {
        int col = n0 + wn + nt * 8 + 2 * c;
        float x0 = bias1 ? __ldg(&bias1[col]) : 0.f;
        float x1 = bias1 ? __ldg(&bias1[col + 1]) : 0.f;
        if (bias2) { x0 += __ldg(&bias2[col]); x1 += __ldg(&bias2[col + 1]); }
        bv0[nt] = x0; bv1[nt] = x1;
    }
#pragma unroll
    for (int mt = 0; mt < 4; mt++) {
        int r0 = m0 + wm + mt * 16 + g;
#pragma unroll
        for (int nt = 0; nt < 4; nt++) {
            int col = n0 + wn + nt * 8 + 2 * c;
            float2 o0 = make_float2(acc[mt][nt][0] + bv0[nt], acc[mt][nt][1] + bv1[nt]);
            float2 o1 = make_float2(acc[mt][nt][2] + bv0[nt], acc[mt][nt][3] + bv1[nt]);
            *(float2*)&C[(size_t)r0 * ldc + col] = o0;
            *(float2*)&C[(size_t)(r0 + 8) * ldc + col] = o1;
        }
    }
}

// ---------------- persistent LSTM layer (tensor-core matvec) -------------------
// 128 CTAs x 256 threads (8 warps). CTA owns 16 gate-rows (m16 tile): tile row
// nl -> global row ng = (nl>>2)*512 + bidx*4 + (nl&3). Warp w owns k-slice
// [w*64, w*64+64): A-fragments (16x64 tf32) live in registers for the whole
// kernel; per step 16 mma.m16n8k8 against h (B) fragments from smem. 8-way
// k-reduce through smem, then 64-thread cell update. h exchanged [k][b].
__global__ __launch_bounds__(LSTM_THREADS, 1) void k_lstm(
    const float* __restrict__ gates_pre,  // [B*T, 2048]
    const float* __restrict__ Whh,        // [2048, 512]
    const float* __restrict__ h_init_t,   // [512][16] transposed
    float* __restrict__ ybase, int ystride,
    float* __restrict__ hfin, float* __restrict__ cfin,
    float* __restrict__ hb0, float* __restrict__ hb1) {
    __shared__ float hs[512 * 16];        // h (tf32 bits) [k][b]  32KB
    __shared__ float pr[8][16][17];       // per-warp partials [w][row][batch]
    __shared__ float gsm[16 * 16];        // reduced gates [nl][b]

    const int tid = threadIdx.x;
    const int bidx = blockIdx.x;
    const int w = tid >> 5, lane = tid & 31;
    const int g = lane >> 2, c = lane & 3;
    const uint32_t* hsu = (const uint32_t*)hs;

    // ---- A-fragments: rows of Whh for this CTA, k-slice of this warp ----
    uint32_t afr[8][4];
    {
        int ng0 = (g >> 2) * 512 + bidx * 4 + (g & 3);             // tile row g
        int ng1 = ((g + 8) >> 2) * 512 + bidx * 4 + (g & 3);       // tile row g+8
        const float* w0 = Whh + (size_t)ng0 * 512;
        const float* w1 = Whh + (size_t)ng1 * 512;
#pragma unroll
        for (int kc = 0; kc < 8; kc++) {
            int kb = w * 64 + kc * 8;
            afr[kc][0] = f2tf32(__ldg(w0 + kb + c));
            afr[kc][1] = f2tf32(__ldg(w1 + kb + c));
            afr[kc][2] = f2tf32(__ldg(w0 + kb + c + 4));
            afr[kc][3] = f2tf32(__ldg(w1 + kb + c + 4));
        }
    }

    // reduce-thread identity (all 256) + gates prefetch
    const int r_nl = tid >> 4, r_b = tid & 15;
    const int r_ng = (r_nl >> 2) * 512 + bidx * 4 + (r_nl & 3);
    float gpre = gates_pre[((size_t)(r_b * T_)) * 2048 + r_ng];

    // cell-update identity (tid < 64)
    float c_reg = 0.f;
    const int cb = tid & 15, chl = (tid >> 4) & 3;
    const int kh = bidx * 4 + chl;

    grid_barrier();

    for (int t = 0; t < T_; t++) {
        const float* hin = (t == 0) ? h_init_t : ((t & 1) ? hb1 : hb0);
        float* hout      = (t & 1) ? hb0 : hb1;

        // stage h -> smem, converting to tf32 (raw [k][b] float4 layout)
#pragma unroll
        for (int i = 0; i < 8; i++) {
            int idx = tid + 256 * i;
            float4 v = __ldcg(((const float4*)hin) + idx);
            sts_cvt4(&hs[idx * 4], v);
        }
        __syncthreads();

        // 16 mma per warp: 8 k-chunks x 2 n-tiles
        float acc0[4] = {0.f, 0.f, 0.f, 0.f};
        float acc1[4] = {0.f, 0.f, 0.f, 0.f};
#pragma unroll
        for (int kc = 0; kc < 8; kc++) {
            int kb = w * 64 + kc * 8;
            uint32_t b0[2], b1[2];
            b0[0] = hsu[(kb + c) * 16 + g];
            b0[1] = hsu[(kb + c + 4) * 16 + g];
            b1[0] = hsu[(kb + c) * 16 + 8 + g];
            b1[1] = hsu[(kb + c + 4) * 16 + 8 + g];
            mma_tf32(acc0, afr[kc], b0);
            mma_tf32(acc1, afr[kc], b1);
        }
        // partials: C[row][batch]
        pr[w][g][2 * c]         = acc0[0];
        pr[w][g][2 * c + 1]     = acc0[1];
        pr[w][g + 8][2 * c]     = acc0[2];
        pr[w][g + 8][2 * c + 1] = acc0[3];
        pr[w][g][8 + 2 * c]         = acc1[0];
        pr[w][g][8 + 2 * c + 1]     = acc1[1];
        pr[w][g + 8][8 + 2 * c]     = acc1[2];
        pr[w][g + 8][8 + 2 * c + 1] = acc1[3];
        __syncthreads();

        // 8-way k-reduce + input gates
        {
            float s = gpre;
#pragma unroll
            for (int q = 0; q < 8; q++) s += pr[q][r_nl][r_b];
            gsm[r_nl * 16 + r_b] = s;
            if (t + 1 < T_)
                gpre = gates_pre[((size_t)(r_b * T_ + t + 1)) * 2048 + r_ng];
        }
        __syncthreads();

        // cell update
        if (tid < 64) {
            float gi = gsm[(0 * 4 + chl) * 16 + cb];
            float gf = gsm[(1 * 4 + chl) * 16 + cb];
            float gg = gsm[(2 * 4 + chl) * 16 + cb];
            float go = gsm[(3 * 4 + chl) * 16 + cb];
            float iv = fsig(gi);
            float fv = fsig(gf);
            float gv = ftanh(gg);
            float ov = fsig(go);
            c_reg = fv * c_reg + iv * gv;
            float hv = ov * ftanh(c_reg);
            hout[kh * 16 + cb] = hv;
            ybase[((size_t)(cb * T_ + t)) * ystride + kh] = hv;
            if (t == T_ - 1) {
                hfin[cb * 512 + kh] = hv;
                cfin[cb * 512 + kh] = c_reg;
            }
        }
        grid_barrier();
    }
}

// ---------------- fused attention: energy + softmax + context -----------------
__global__ __launch_bounds__(256) void k_attn(
    const float* __restrict__ encf, const float* __restrict__ decf,
    const float* __restrict__ mem, const unsigned char* __restrict__ mask,
    const float* __restrict__ v, const float* __restrict__ vb,
    float* __restrict__ outcat) {
    __shared__ float df[8][512];
    __shared__ float vsh[512];
    __shared__ float row[512];
    __shared__ float en[8][128];
    const int b = blockIdx.x;
    const int t0 = blockIdx.y * 8;
    const int tid = threadIdx.x;
    const int w = tid >> 5, lane = tid & 31;

    for (int i = tid; i < 512; i += 256) vsh[i] = v[i];
    for (int i = tid; i < 8 * 512; i += 256) {
        int jj = i >> 9, h = i & 511;
        df[jj][h] = decf[((size_t)(b * T_ + t0 + jj)) * 512 + h];
    }
    __syncthreads();
    const float vbv = vb[0];

    for (int s = 0; s < S_; s++) {
        for (int i = tid; i < 512; i += 256) row[i] = encf[((size_t)(b * S_ + s)) * 512 + i];
        __syncthreads();
        float e = 0.f;
#pragma unroll
        for (int i = 0; i < 16; i++) {
            int h = lane + 32 * i;
            e = fmaf(vsh[h], ftanh(row[h] + df[w][h]), e);
        }
#pragma unroll
        for (int off = 16; off; off >>= 1) e += __shfl_xor_sync(0xffffffffu, e, off);
        if (lane == 0) {
            e += vbv;
            if (mask[b * S_ + s]) e = -1e9f;
            en[w][s] = e;
        }
        __syncthreads();
    }

    {
        float vals[4];
        float m = -1e30f;
#pragma unroll
        for (int i = 0; i < 4; i++) { vals[i] = en[w][lane + 32 * i]; m = fmaxf(m, vals[i]); }
#pragma unroll
        for (int off = 16; off; off >>= 1) m = fmaxf(m, __shfl_xor_sync(0xffffffffu, m, off));
        float ssum = 0.f;
#pragma unroll
        for (int i = 0; i < 4; i++) { vals[i] = __expf(vals[i] - m); ssum += vals[i]; }
#pragma unroll
        for (int off = 16; off; off >>= 1) ssum += __shfl_xor_sync(0xffffffffu, ssum, off);
        float inv = 1.f / ssum;
#pragma unroll
        for (int i = 0; i < 4; i++) en[w][lane + 32 * i] = vals[i] * inv;
    }
    __syncthreads();

    float c0[8], c1[8];
#pragma unroll
    for (int jj = 0; jj < 8; jj++) { c0[jj] = 0.f; c1[jj] = 0.f; }
    for (int s = 0; s < S_; s++) {
        for (int i = tid; i < 512; i += 256) row[i] = mem[((size_t)(b * S_ + s)) * 512 + i];
        __syncthreads();
        float m0 = row[tid], m1 = row[tid + 256];
#pragma unroll
        for (int jj = 0; jj < 8; jj++) {
            float a = en[jj][s];
            c0[jj] = fmaf(a, m0, c0[jj]);
            c1[jj] = fmaf(a, m1, c1[jj]);
        }
        __syncthreads();
    }
#pragma unroll
    for (int jj = 0; jj < 8; jj++) {
        size_t rr = ((size_t)(b * T_ + t0 + jj)) * 1024 + 512;
        outcat[rr + tid] = c0[jj];
        outcat[rr + tid + 256] = c1[jj];
    }
}

// ---------------- launch -------------------------------------------------------
extern "C" void kernel_launch(void* const* d_in, const int* in_sizes, int n_in,
                              void* d_out, int out_size) {
    (void)in_sizes; (void)n_in; (void)out_size;
    const int*   tgt  = (const int*)d_in[0];
    const float* mem  = (const float*)d_in[1];
    const unsigned char* mask = (const unsigned char*)d_in[2];
    const float* emb  = (const float*)d_in[3];
    const float* Wih0 = (const float*)d_in[4];
    const float* Whh0 = (const float*)d_in[5];
    const float* bih0 = (const float*)d_in[6];
    const float* bhh0 = (const float*)d_in[7];
    const float* Wih1 = (const float*)d_in[8];
    const float* Whh1 = (const float*)d_in[9];
    const float* bih1 = (const float*)d_in[10];
    const float* bhh1 = (const float*)d_in[11];
    const float* Wh   = (const float*)d_in[12];
    const float* bh   = (const float*)d_in[13];
    const float* Ws   = (const float*)d_in[14];
    const float* bs   = (const float*)d_in[15];
    const float* v    = (const float*)d_in[16];
    const float* vb   = (const float*)d_in[17];
    const float* Wout = (const float*)d_in[18];
    const float* bout = (const float*)d_in[19];

    float* out = (float*)d_out;
    float* logits = out;
    float* hn = out + (size_t)B_ * T_ * V_;
    float* cn = hn + 2 * B_ * H_;

    float *px, *pgates, *py1, *pcat, *pencf, *pdecf, *pench, *ph0, *ph1;
    cudaGetSymbolAddress((void**)&px, g_x);
    cudaGetSymbolAddress((void**)&pgates, g_gates);
    cudaGetSymbolAddress((void**)&py1, g_y1);
    cudaGetSymbolAddress((void**)&pcat, g_cat);
    cudaGetSymbolAddress((void**)&pencf, g_encf);
    cudaGetSymbolAddress((void**)&pdecf, g_decf);
    cudaGetSymbolAddress((void**)&pench, g_ench_t);
    cudaGetSymbolAddress((void**)&ph0, g_h0);
    cudaGetSymbolAddress((void**)&ph1, g_h1);

    // 1. embedding + enc_hidden (transposed)
    k_embed<<<2048, 128>>>(tgt, emb, px);
    k_mean<<<B_, 512>>>(mem, pench);

    // 2. layer0 input gates (tf32 mma), layer0 recurrence
    gemm_tf32<<<dim3(16, 16), 256>>>(px, 512, Wih0, 512, 512, bih0, bhh0, pgates, 2048);
    k_lstm<<<LSTM_BLOCKS, LSTM_THREADS>>>(pgates, Whh0, pench, py1, 512,
                                          hn, cn, ph0, ph1);

    // 3. layer1 input gates, layer1 recurrence (y2 -> first half of g_cat)
    gemm_tf32<<<dim3(16, 16), 256>>>(py1, 512, Wih1, 512, 512, bih1, bhh1, pgates, 2048);
    k_lstm<<<LSTM_BLOCKS, LSTM_THREADS>>>(pgates, Whh1, pench, pcat, 1024,
                                          hn + B_ * H_, cn + B_ * H_, ph0, ph1);

    // 4. attention features
    gemm_tf32<<<dim3(4, 16), 256>>>(mem, 512, Wh, 512, 512, bh, nullptr, pencf, 512);
    gemm_tf32<<<dim3(4, 16), 256>>>(pcat, 1024, Ws, 512, 512, bs, nullptr, pdecf, 512);

    // 5. fused energy/softmax/context -> second half of g_cat
    k_attn<<<dim3(B_, T_ / 8), 256>>>(pencf, pdecf, mem, mask, v, vb, pcat);

    // 6. output projection (tf32 mma)
    gemm_tf32<<<dim3(32, 16), 256>>>(pcat, 1024, Wout, 1024, 1024, bout, nullptr, logits, 4096);
}

// round 6
// speedup vs baseline: 1.4462x; 1.1687x over previous
#include <cuda_runtime.h>
#include <math.h>
#include <stdint.h>

#define B_ 16
#define T_ 128
#define S_ 128
#define E_ 512
#define H_ 512
#define V_ 4096

#define TOT_CTAS 256
#define LSTM_THREADS 256
// dynamic smem: hs 32KB + xs 32KB + pr 8.5KB + gsm 1KB
#define LSTM_SMEM (32768 + 32768 + 8704 + 1024)

// ---------------- scratch (device globals; no cudaMalloc allowed) -------------
__device__ float g_x[2048 * 512];        // embedded input [B*T, E]
__device__ float g_gates[2048 * 2048];   // precomputed layer0 input gates [B*T, 4H]
__device__ float g_cat[2048 * 1024];     // [y2 | context]  [B*T, H+E]
__device__ float g_encf[2048 * 512];     // enc_feat [B*S, H]
__device__ float g_decf[2048 * 512];     // dec_feat [B*T, H]
__device__ float g_ench_t[512 * 16];     // enc_hidden TRANSPOSED [k][b]
__device__ float g_h0a[512 * 16];        // layer0 h exchange (parity 0)
__device__ float g_h0b[512 * 16];        // layer0 h exchange (parity 1)
__device__ float g_h1a[512 * 16];        // layer1 h exchange (parity 0)
__device__ float g_h1b[512 * 16];        // layer1 h exchange (parity 1)
__device__ float g_y1a[512 * 16];        // y1 cross-layer exchange (parity 0)
__device__ float g_y1b[512 * 16];        // y1 cross-layer exchange (parity 1)
__device__ unsigned long long g_bar_cnt; // zero-initialized, monotone

// ---------------- fast activations ---------------------------------------------
__device__ __forceinline__ float fsig(float x)  { return 1.f / (1.f + __expf(-x)); }
__device__ __forceinline__ float ftanh(float x) { return 1.f - 2.f / (__expf(2.f * x) + 1.f); }

// ---------------- grid barrier (release/acquire, fence only on tid0) ----------
__device__ __forceinline__ void grid_barrier() {
    __syncthreads();
    if (threadIdx.x == 0) {
        unsigned long long old, cur;
        asm volatile("atom.add.release.gpu.u64 %0, [%1], 1;"
                     : "=l"(old) : "l"(&g_bar_cnt) : "memory");
        unsigned long long target = (old / TOT_CTAS + 1ULL) * TOT_CTAS;
        do {
            asm volatile("ld.acquire.gpu.u64 %0, [%1];"
                         : "=l"(cur) : "l"(&g_bar_cnt) : "memory");
            if (cur < target) __nanosleep(20);
        } while (cur < target);
    }
    __syncthreads();
}

// ---------------- embedding gather --------------------------------------------
__global__ void k_embed(const int* __restrict__ tgt, const float* __restrict__ emb,
                        float* __restrict__ x) {
    int r = blockIdx.x;
    int tok = tgt[r];
    ((float4*)x)[r * 128 + threadIdx.x] = ((const float4*)emb)[tok * 128 + threadIdx.x];
}

// ---------------- mean over source positions (writes TRANSPOSED [e][b]) -------
__global__ void k_mean(const float* __restrict__ mem, float* __restrict__ out_t) {
    int b = blockIdx.x;
    int e = threadIdx.x;
    float s = 0.f;
    for (int t = 0; t < S_; t++) s += mem[(b * S_ + t) * 512 + e];
    out_t[e * 16 + b] = s * (1.f / (float)S_);
}

// ---------------- tf32 helpers --------------------------------------------------
__device__ __forceinline__ uint32_t f2tf32(float f) {
    uint32_t u; asm("cvt.rna.tf32.f32 %0, %1;" : "=r"(u) : "f"(f)); return u;
}
__device__ __forceinline__ void mma_tf32(float* d, const uint32_t* a, const uint32_t* b) {
    asm volatile("mma.sync.aligned.m16n8k8.row.col.f32.tf32.tf32.f32 "
        "{%0,%1,%2,%3}, {%4,%5,%6,%7}, {%8,%9}, {%0,%1,%2,%3};"
        : "+f"(d[0]), "+f"(d[1]), "+f"(d[2]), "+f"(d[3])
        : "r"(a[0]), "r"(a[1]), "r"(a[2]), "r"(a[3]), "r"(b[0]), "r"(b[1]));
}
__device__ __forceinline__ void sts_cvt4(float* dst, float4 v) {
    uint4 u;
    u.x = f2tf32(v.x); u.y = f2tf32(v.y); u.z = f2tf32(v.z); u.w = f2tf32(v.w);
    *(uint4*)dst = u;
}

// ---------------- tf32 tensor-core GEMM ----------------------------------------
__global__ __launch_bounds__(256, 2) void gemm_tf32(
    const float* __restrict__ A, int lda,
    const float* __restrict__ W, int ldw, int K,
    const float* __restrict__ bias1, const float* __restrict__ bias2,
    float* __restrict__ C, int ldc) {
    __shared__ float As[128 * 20];
    __shared__ float Bs[128 * 20];
    const int tid = threadIdx.x;
    const int m0 = blockIdx.y * 128, n0 = blockIdx.x * 128;
    const int warp = tid >> 5, lane = tid & 31;
    const int wm = (warp & 1) * 64;
    const int wn = (warp >> 1) * 32;
    const int g = lane >> 2, c = lane & 3;

    const int lr = tid >> 2;
    const int lq = tid & 3;
    const float* Ap = A + (size_t)(m0 + lr) * lda + lq * 4;
    const float* Wp = W + (size_t)(n0 + lr) * ldw + lq * 4;
    const size_t astep = (size_t)64 * lda;
    const size_t wstep = (size_t)64 * ldw;

    float4 ar0 = *(const float4*)(Ap);
    float4 ar1 = *(const float4*)(Ap + astep);
    float4 br0 = *(const float4*)(Wp);
    float4 br1 = *(const float4*)(Wp + wstep);

    float acc[4][4][4];
#pragma unroll
    for (int i = 0; i < 4; i++)
#pragma unroll
        for (int j = 0; j < 4; j++)
#pragma unroll
            for (int q = 0; q < 4; q++) acc[i][j][q] = 0.f;

    const int nkt = K >> 4;
    for (int kt = 0; kt < nkt; kt++) {
        __syncthreads();
        sts_cvt4(&As[lr * 20 + lq * 4], ar0);
        sts_cvt4(&As[(lr + 64) * 20 + lq * 4], ar1);
        sts_cvt4(&Bs[lr * 20 + lq * 4], br0);
        sts_cvt4(&Bs[(lr + 64) * 20 + lq * 4], br1);
        __syncthreads();
        if (kt + 1 < nkt) {
            const float* Ap2 = Ap + (kt + 1) * 16;
            const float* Wp2 = Wp + (kt + 1) * 16;
            ar0 = *(const float4*)(Ap2);
            ar1 = *(const float4*)(Ap2 + astep);
            br0 = *(const float4*)(Wp2);
            br1 = *(const float4*)(Wp2 + wstep);
        }
#pragma unroll
        for (int kk = 0; kk < 16; kk += 8) {
            uint32_t af[4][4];
            uint32_t bf[4][2];
#pragma unroll
            for (int mt = 0; mt < 4; mt++) {
                int mr = wm + mt * 16 + g;
                af[mt][0] = __float_as_uint(As[mr * 20 + kk + c]);
                af[mt][1] = __float_as_uint(As[(mr + 8) * 20 + kk + c]);
                af[mt][2] = __float_as_uint(As[mr * 20 + kk + c + 4]);
                af[mt][3] = __float_as_uint(As[(mr + 8) * 20 + kk + c + 4]);
            }
#pragma unroll
            for (int nt = 0; nt < 4; nt++) {
                int nr = wn + nt * 8 + g;
                bf[nt][0] = __float_as_uint(Bs[nr * 20 + kk + c]);
                bf[nt][1] = __float_as_uint(Bs[nr * 20 + kk + c + 4]);
            }
#pragma unroll
            for (int mt = 0; mt < 4; mt++)
#pragma unroll
                for (int nt = 0; nt < 4; nt++)
                    mma_tf32(acc[mt][nt], af[mt], bf[nt]);
        }
    }

    float bv0[4], bv1[4];
#pragma unroll
    for (int nt = 0; nt < 4; nt++) {
        int col = n0 + wn + nt * 8 + 2 * c;
        float x0 = bias1 ? __ldg(&bias1[col]) : 0.f;
        float x1 = bias1 ? __ldg(&bias1[col + 1]) : 0.f;
        if (bias2) { x0 += __ldg(&bias2[col]); x1 += __ldg(&bias2[col + 1]); }
        bv0[nt] = x0; bv1[nt] = x1;
    }
#pragma unroll
    for (int mt = 0; mt < 4; mt++) {
        int r0 = m0 + wm + mt * 16 + g;
#pragma unroll
        for (int nt = 0; nt < 4; nt++) {
            int col = n0 + wn + nt * 8 + 2 * c;
            float2 o0 = make_float2(acc[mt][nt][0] + bv0[nt], acc[mt][nt][1] + bv1[nt]);
            float2 o1 = make_float2(acc[mt][nt][2] + bv0[nt], acc[mt][nt][3] + bv1[nt]);
            *(float2*)&C[(size_t)r0 * ldc + col] = o0;
            *(float2*)&C[(size_t)(r0 + 8) * ldc + col] = o1;
        }
    }
}

// ---------------- fused 2-layer pipelined persistent LSTM ----------------------
// 256 CTAs: blockIdx>>7 = layer, &127 = bidx (owns h indices bidx*4..+3).
// Global step s: layer0 computes t=s (s<T), layer1 computes t=s-1 (s>=1).
// Layer1 computes its input gates on the fly (Wih1 @ y1[t]) with a second
// register-resident fragment set accumulated into the same MMA accumulators.
__global__ __launch_bounds__(LSTM_THREADS, 2) void k_lstm2(
    const float* __restrict__ gates0,     // [B*T, 2048] layer0 input gates (w/ biases)
    const float* __restrict__ Whh0,
    const float* __restrict__ Wih1,
    const float* __restrict__ Whh1,
    const float* __restrict__ bih1, const float* __restrict__ bhh1,
    const float* __restrict__ h_init_t,   // [512][16]
    float* __restrict__ ycat,             // y2 -> g_cat [b][t][1024]
    float* __restrict__ hn, float* __restrict__ cn,  // [2,B,H]
    float* __restrict__ h0a, float* __restrict__ h0b,
    float* __restrict__ h1a, float* __restrict__ h1b,
    float* __restrict__ y1a, float* __restrict__ y1b) {
    extern __shared__ float smf[];
    float* hs = smf;                         // [512*16] tf32 bits
    float* xs = smf + 512 * 16;              // [512*16] tf32 bits (layer1 only)
    float (*pr)[16][17] = (float(*)[16][17])(smf + 2 * 512 * 16);
    float* gsm = smf + 2 * 512 * 16 + 8 * 16 * 17;

    const int tid = threadIdx.x;
    const int layer = blockIdx.x >> 7;
    const int bidx = blockIdx.x & 127;
    const int w = tid >> 5, lane = tid & 31;
    const int g = lane >> 2, c = lane & 3;
    const uint32_t* hsu = (const uint32_t*)hs;
    const uint32_t* xsu = (const uint32_t*)xs;

    // ---- A fragments ----
    uint32_t afr_h[8][4];
    uint32_t afr_x[8][4];
    {
        const float* Wh_ = layer ? Whh1 : Whh0;
        int ng0 = (g >> 2) * 512 + bidx * 4 + (g & 3);
        int ng1 = ((g + 8) >> 2) * 512 + bidx * 4 + (g & 3);
        const float* w0 = Wh_ + (size_t)ng0 * 512;
        const float* w1 = Wh_ + (size_t)ng1 * 512;
#pragma unroll
        for (int kc = 0; kc < 8; kc++) {
            int kb = w * 64 + kc * 8;
            afr_h[kc][0] = f2tf32(__ldg(w0 + kb + c));
            afr_h[kc][1] = f2tf32(__ldg(w1 + kb + c));
            afr_h[kc][2] = f2tf32(__ldg(w0 + kb + c + 4));
            afr_h[kc][3] = f2tf32(__ldg(w1 + kb + c + 4));
        }
        if (layer) {
            const float* x0 = Wih1 + (size_t)ng0 * 512;
            const float* x1 = Wih1 + (size_t)ng1 * 512;
#pragma unroll
            for (int kc = 0; kc < 8; kc++) {
                int kb = w * 64 + kc * 8;
                afr_x[kc][0] = f2tf32(__ldg(x0 + kb + c));
                afr_x[kc][1] = f2tf32(__ldg(x1 + kb + c));
                afr_x[kc][2] = f2tf32(__ldg(x0 + kb + c + 4));
                afr_x[kc][3] = f2tf32(__ldg(x1 + kb + c + 4));
            }
        }
    }

    // reduce-thread identity + per-layer gate base
    const int r_nl = tid >> 4, r_b = tid & 15;
    const int r_ng = (r_nl >> 2) * 512 + bidx * 4 + (r_nl & 3);
    float gpre;                    // layer0: prefetched gates0; layer1: bias sum
    if (layer) gpre = __ldg(&bih1[r_ng]) + __ldg(&bhh1[r_ng]);
    else       gpre = gates0[((size_t)(r_b * T_)) * 2048 + r_ng];

    // cell-update identity (tid < 64)
    float c_reg = 0.f;
    const int cb = tid & 15, chl = (tid >> 4) & 3;
    const int kh = bidx * 4 + chl;

    grid_barrier();

    for (int s = 0; s <= T_; s++) {
        const int t = layer ? (s - 1) : s;
        const bool active = layer ? (s >= 1) : (s < T_);
        if (active) {
            // select buffers
            const float* hin;
            float* hout;
            if (layer == 0) {
                hin  = (t == 0) ? h_init_t : ((t & 1) ? h0a : h0b);  // read 1-parity
                hout = (t & 1) ? h0b : h0a;
            } else {
                hin  = (t == 0) ? h_init_t : ((t & 1) ? h1a : h1b);
                hout = (t & 1) ? h1b : h1a;
            }
            const float* xin = (t & 1) ? y1b : y1a;   // layer1 input y1[t]
            float* yout = (t & 1) ? y1b : y1a;        // layer0 writes y1[t]

            // stage h (+ y1 for layer1) -> smem as tf32
#pragma unroll
            for (int i = 0; i < 8; i++) {
                int idx = tid + 256 * i;
                float4 vh = __ldcg(((const float4*)hin) + idx);
                sts_cvt4(&hs[idx * 4], vh);
            }
            if (layer) {
#pragma unroll
                for (int i = 0; i < 8; i++) {
                    int idx = tid + 256 * i;
                    float4 vx = __ldcg(((const float4*)xin) + idx);
                    sts_cvt4(&xs[idx * 4], vx);
                }
            }
            __syncthreads();

            // MMA: h matvec (+ x matvec for layer1), same accumulators
            float acc0[4] = {0.f, 0.f, 0.f, 0.f};
            float acc1[4] = {0.f, 0.f, 0.f, 0.f};
#pragma unroll
            for (int kc = 0; kc < 8; kc++) {
                int kb = w * 64 + kc * 8;
                uint32_t b0[2], b1[2];
                b0[0] = hsu[(kb + c) * 16 + g];
                b0[1] = hsu[(kb + c + 4) * 16 + g];
                b1[0] = hsu[(kb + c) * 16 + 8 + g];
                b1[1] = hsu[(kb + c + 4) * 16 + 8 + g];
                mma_tf32(acc0, afr_h[kc], b0);
                mma_tf32(acc1, afr_h[kc], b1);
            }
            if (layer) {
#pragma unroll
                for (int kc = 0; kc < 8; kc++) {
                    int kb = w * 64 + kc * 8;
                    uint32_t b0[2], b1[2];
                    b0[0] = xsu[(kb + c) * 16 + g];
                    b0[1] = xsu[(kb + c + 4) * 16 + g];
                    b1[0] = xsu[(kb + c) * 16 + 8 + g];
                    b1[1] = xsu[(kb + c + 4) * 16 + 8 + g];
                    mma_tf32(acc0, afr_x[kc], b0);
                    mma_tf32(acc1, afr_x[kc], b1);
                }
            }
            pr[w][g][2 * c]         = acc0[0];
            pr[w][g][2 * c + 1]     = acc0[1];
            pr[w][g + 8][2 * c]     = acc0[2];
            pr[w][g + 8][2 * c + 1] = acc0[3];
            pr[w][g][8 + 2 * c]         = acc1[0];
            pr[w][g][8 + 2 * c + 1]     = acc1[1];
            pr[w][g + 8][8 + 2 * c]     = acc1[2];
            pr[w][g + 8][8 + 2 * c + 1] = acc1[3];
            __syncthreads();

            // 8-way k-reduce + gate base
            {
                float sum = gpre;
#pragma unroll
                for (int q = 0; q < 8; q++) sum += pr[q][r_nl][r_b];
                gsm[r_nl * 16 + r_b] = sum;
                if (layer == 0 && t + 1 < T_)
                    gpre = gates0[((size_t)(r_b * T_ + t + 1)) * 2048 + r_ng];
            }
            __syncthreads();

            // cell update
            if (tid < 64) {
                float gi = gsm[(0 * 4 + chl) * 16 + cb];
                float gf = gsm[(1 * 4 + chl) * 16 + cb];
                float gg = gsm[(2 * 4 + chl) * 16 + cb];
                float go = gsm[(3 * 4 + chl) * 16 + cb];
                float iv = fsig(gi);
                float fv = fsig(gf);
                float gv = ftanh(gg);
                float ov = fsig(go);
                c_reg = fv * c_reg + iv * gv;
                float hv = ov * ftanh(c_reg);
                hout[kh * 16 + cb] = hv;
                if (layer == 0) {
                    yout[kh * 16 + cb] = hv;
                    if (t == T_ - 1) {
                        hn[cb * 512 + kh] = hv;
                        cn[cb * 512 + kh] = c_reg;
                    }
                } else {
                    ycat[((size_t)(cb * T_ + t)) * 1024 + kh] = hv;
                    if (t == T_ - 1) {
                        hn[B_ * H_ + cb * 512 + kh] = hv;
                        cn[B_ * H_ + cb * 512 + kh] = c_reg;
                    }
                }
            }
        }
        grid_barrier();
    }
}

// ---------------- fused attention: energy + softmax + context -----------------
__global__ __launch_bounds__(256) void k_attn(
    const float* __restrict__ encf, const float* __restrict__ decf,
    const float* __restrict__ mem, const unsigned char* __restrict__ mask,
    const float* __restrict__ v, const float* __restrict__ vb,
    float* __restrict__ outcat) {
    __shared__ float df[8][512];
    __shared__ float vsh[512];
    __shared__ float row[512];
    __shared__ float en[8][128];
    const int b = blockIdx.x;
    const int t0 = blockIdx.y * 8;
    const int tid = threadIdx.x;
    const int w = tid >> 5, lane = tid & 31;

    for (int i = tid; i < 512; i += 256) vsh[i] = v[i];
    for (int i = tid; i < 8 * 512; i += 256) {
        int jj = i >> 9, h = i & 511;
        df[jj][h] = decf[((size_t)(b * T_ + t0 + jj)) * 512 + h];
    }
    __syncthreads();
    const float vbv = vb[0];

    for (int s = 0; s < S_; s++) {
        for (int i = tid; i < 512; i += 256) row[i] = encf[((size_t)(b * S_ + s)) * 512 + i];
        __syncthreads();
        float e = 0.f;
#pragma unroll
        for (int i = 0; i < 16; i++) {
            int h = lane + 32 * i;
            e = fmaf(vsh[h], ftanh(row[h] + df[w][h]), e);
        }
#pragma unroll
        for (int off = 16; off; off >>= 1) e += __shfl_xor_sync(0xffffffffu, e, off);
        if (lane == 0) {
            e += vbv;
            if (mask[b * S_ + s]) e = -1e9f;
            en[w][s] = e;
        }
        __syncthreads();
    }

    {
        float vals[4];
        float m = -1e30f;
#pragma unroll
        for (int i = 0; i < 4; i++) { vals[i] = en[w][lane + 32 * i]; m = fmaxf(m, vals[i]); }
#pragma unroll
        for (int off = 16; off; off >>= 1) m = fmaxf(m, __shfl_xor_sync(0xffffffffu, m, off));
        float ssum = 0.f;
#pragma unroll
        for (int i = 0; i < 4; i++) { vals[i] = __expf(vals[i] - m); ssum += vals[i]; }
#pragma unroll
        for (int off = 16; off; off >>= 1) ssum += __shfl_xor_sync(0xffffffffu, ssum, off);
        float inv = 1.f / ssum;
#pragma unroll
        for (int i = 0; i < 4; i++) en[w][lane + 32 * i] = vals[i] * inv;
    }
    __syncthreads();

    float c0[8], c1[8];
#pragma unroll
    for (int jj = 0; jj < 8; jj++) { c0[jj] = 0.f; c1[jj] = 0.f; }
    for (int s = 0; s < S_; s++) {
        for (int i = tid; i < 512; i += 256) row[i] = mem[((size_t)(b * S_ + s)) * 512 + i];
        __syncthreads();
        float m0 = row[tid], m1 = row[tid + 256];
#pragma unroll
        for (int jj = 0; jj < 8; jj++) {
            float a = en[jj][s];
            c0[jj] = fmaf(a, m0, c0[jj]);
            c1[jj] = fmaf(a, m1, c1[jj]);
        }
        __syncthreads();
    }
#pragma unroll
    for (int jj = 0; jj < 8; jj++) {
        size_t rr = ((size_t)(b * T_ + t0 + jj)) * 1024 + 512;
        outcat[rr + tid] = c0[jj];
        outcat[rr + tid + 256] = c1[jj];
    }
}

// ---------------- launch -------------------------------------------------------
extern "C" void kernel_launch(void* const* d_in, const int* in_sizes, int n_in,
                              void* d_out, int out_size) {
    (void)in_sizes; (void)n_in; (void)out_size;
    const int*   tgt  = (const int*)d_in[0];
    const float* mem  = (const float*)d_in[1];
    const unsigned char* mask = (const unsigned char*)d_in[2];
    const float* emb  = (const float*)d_in[3];
    const float* Wih0 = (const float*)d_in[4];
    const float* Whh0 = (const float*)d_in[5];
    const float* bih0 = (const float*)d_in[6];
    const float* bhh0 = (const float*)d_in[7];
    const float* Wih1 = (const float*)d_in[8];
    const float* Whh1 = (const float*)d_in[9];
    const float* bih1 = (const float*)d_in[10];
    const float* bhh1 = (const float*)d_in[11];
    const float* Wh   = (const float*)d_in[12];
    const float* bh   = (const float*)d_in[13];
    const float* Ws   = (const float*)d_in[14];
    const float* bs   = (const float*)d_in[15];
    const float* v    = (const float*)d_in[16];
    const float* vb   = (const float*)d_in[17];
    const float* Wout = (const float*)d_in[18];
    const float* bout = (const float*)d_in[19];

    float* out = (float*)d_out;
    float* logits = out;
    float* hn = out + (size_t)B_ * T_ * V_;
    float* cn = hn + 2 * B_ * H_;

    float *px, *pgates, *pcat, *pencf, *pdecf, *pench;
    float *ph0a, *ph0b, *ph1a, *ph1b, *py1a, *py1b;
    cudaGetSymbolAddress((void**)&px, g_x);
    cudaGetSymbolAddress((void**)&pgates, g_gates);
    cudaGetSymbolAddress((void**)&pcat, g_cat);
    cudaGetSymbolAddress((void**)&pencf, g_encf);
    cudaGetSymbolAddress((void**)&pdecf, g_decf);
    cudaGetSymbolAddress((void**)&pench, g_ench_t);
    cudaGetSymbolAddress((void**)&ph0a, g_h0a);
    cudaGetSymbolAddress((void**)&ph0b, g_h0b);
    cudaGetSymbolAddress((void**)&ph1a, g_h1a);
    cudaGetSymbolAddress((void**)&ph1b, g_h1b);
    cudaGetSymbolAddress((void**)&py1a, g_y1a);
    cudaGetSymbolAddress((void**)&py1b, g_y1b);

    cudaFuncSetAttribute(k_lstm2, cudaFuncAttributeMaxDynamicSharedMemorySize, LSTM_SMEM);

    // 1. embedding + enc_hidden (transposed)
    k_embed<<<2048, 128>>>(tgt, emb, px);
    k_mean<<<B_, 512>>>(mem, pench);

    // 2. attention enc features (independent of LSTM; run before to keep tail short)
    gemm_tf32<<<dim3(4, 16), 256>>>(mem, 512, Wh, 512, 512, bh, nullptr, pencf, 512);

    // 3. layer0 input gates (tf32 mma)
    gemm_tf32<<<dim3(16, 16), 256>>>(px, 512, Wih0, 512, 512, bih0, bhh0, pgates, 2048);

    // 4. fused pipelined 2-layer LSTM (y2 -> first half of g_cat)
    k_lstm2<<<TOT_CTAS, LSTM_THREADS, LSTM_SMEM>>>(
        pgates, Whh0, Wih1, Whh1, bih1, bhh1, pench,
        pcat, hn, cn, ph0a, ph0b, ph1a, ph1b, py1a, py1b);

    // 5. dec features
    gemm_tf32<<<dim3(4, 16), 256>>>(pcat, 1024, Ws, 512, 512, bs, nullptr, pdecf, 512);

    // 6. fused energy/softmax/context -> second half of g_cat
    k_attn<<<dim3(B_, T_ / 8), 256>>>(pencf, pdecf, mem, mask, v, vb, pcat);

    // 7. output projection (tf32 mma)
    gemm_tf32<<<dim3(32, 16), 256>>>(pcat, 1024, Wout, 1024, 1024, bout, nullptr, logits, 4096);
}

// round 7
// speedup vs baseline: 1.6892x; 1.1680x over previous
#include <cuda_runtime.h>
#include <math.h>
#include <stdint.h>

#define B_ 16
#define T_ 128
#define S_ 128
#define E_ 512
#define H_ 512
#define V_ 4096

#define TOT_CTAS 256
#define LSTM_THREADS 256
// dynamic smem: hs 32KB + xs 32KB + pr 8.5KB + gsm 1KB
#define LSTM_SMEM (32768 + 32768 + 8704 + 1024)

// ---------------- scratch (device globals; no cudaMalloc allowed) -------------
__device__ float g_x[2048 * 512];        // embedded input [B*T, E]
__device__ float g_gates[2048 * 2048];   // precomputed layer0 input gates [B*T, 4H]
__device__ float g_cat[2048 * 1024];     // [y2 | context]  [B*T, H+E]
__device__ float g_encf[2048 * 512];     // enc_feat [B*S, H]
__device__ float g_decf[2048 * 512];     // dec_feat [B*T, H]
__device__ float g_ench_t[512 * 16];     // enc_hidden TRANSPOSED [k][b]
__device__ float g_h0a[512 * 16];        // layer0 h exchange (parity 0)
__device__ float g_h0b[512 * 16];        // layer0 h exchange (parity 1)
__device__ float g_h1a[512 * 16];        // layer1 h exchange (parity 0)
__device__ float g_h1b[512 * 16];        // layer1 h exchange (parity 1)
__device__ float g_y1a[512 * 16];        // y1 cross-layer exchange (parity 0)
__device__ float g_y1b[512 * 16];        // y1 cross-layer exchange (parity 1)
__device__ unsigned long long g_bar_cnt; // zero-initialized, monotone

// ---------------- fast activations (single-MUFU tanh.approx) -------------------
__device__ __forceinline__ float ftanh(float x) {
    float y; asm("tanh.approx.f32 %0, %1;" : "=f"(y) : "f"(x)); return y;
}
__device__ __forceinline__ float fsig(float x) {
    return 0.5f * ftanh(0.5f * x) + 0.5f;
}

// ---------------- grid barrier (release/acquire, fence only on tid0) ----------
__device__ __forceinline__ void grid_barrier() {
    __syncthreads();
    if (threadIdx.x == 0) {
        unsigned long long old, cur;
        asm volatile("atom.add.release.gpu.u64 %0, [%1], 1;"
                     : "=l"(old) : "l"(&g_bar_cnt) : "memory");
        unsigned long long target = (old / TOT_CTAS + 1ULL) * TOT_CTAS;
        do {
            asm volatile("ld.acquire.gpu.u64 %0, [%1];"
                         : "=l"(cur) : "l"(&g_bar_cnt) : "memory");
            if (cur < target) __nanosleep(20);
        } while (cur < target);
    }
    __syncthreads();
}

// ---------------- embedding gather --------------------------------------------
__global__ void k_embed(const int* __restrict__ tgt, const float* __restrict__ emb,
                        float* __restrict__ x) {
    int r = blockIdx.x;
    int tok = tgt[r];
    ((float4*)x)[r * 128 + threadIdx.x] = ((const float4*)emb)[tok * 128 + threadIdx.x];
}

// ---------------- mean over source positions (writes TRANSPOSED [e][b]) -------
__global__ void k_mean(const float* __restrict__ mem, float* __restrict__ out_t) {
    int b = blockIdx.x;
    int e = threadIdx.x;
    float s = 0.f;
    for (int t = 0; t < S_; t++) s += mem[(b * S_ + t) * 512 + e];
    out_t[e * 16 + b] = s * (1.f / (float)S_);
}

// ---------------- tf32 helpers --------------------------------------------------
__device__ __forceinline__ uint32_t f2tf32(float f) {
    uint32_t u; asm("cvt.rna.tf32.f32 %0, %1;" : "=r"(u) : "f"(f)); return u;
}
__device__ __forceinline__ void mma_tf32(float* d, const uint32_t* a, const uint32_t* b) {
    asm volatile("mma.sync.aligned.m16n8k8.row.col.f32.tf32.tf32.f32 "
        "{%0,%1,%2,%3}, {%4,%5,%6,%7}, {%8,%9}, {%0,%1,%2,%3};"
        : "+f"(d[0]), "+f"(d[1]), "+f"(d[2]), "+f"(d[3])
        : "r"(a[0]), "r"(a[1]), "r"(a[2]), "r"(a[3]), "r"(b[0]), "r"(b[1]));
}
__device__ __forceinline__ void sts_cvt4(float* dst, float4 v) {
    uint4 u;
    u.x = f2tf32(v.x); u.y = f2tf32(v.y); u.z = f2tf32(v.z); u.w = f2tf32(v.w);
    *(uint4*)dst = u;
}

// ---------------- tf32 tensor-core GEMM ----------------------------------------
__global__ __launch_bounds__(256, 2) void gemm_tf32(
    const float* __restrict__ A, int lda,
    const float* __restrict__ W, int ldw, int K,
    const float* __restrict__ bias1, const float* __restrict__ bias2,
    float* __restrict__ C, int ldc) {
    __shared__ float As[128 * 20];
    __shared__ float Bs[128 * 20];
    const int tid = threadIdx.x;
    const int m0 = blockIdx.y * 128, n0 = blockIdx.x * 128;
    const int warp = tid >> 5, lane = tid & 31;
    const int wm = (warp & 1) * 64;
    const int wn = (warp >> 1) * 32;
    const int g = lane >> 2, c = lane & 3;

    const int lr = tid >> 2;
    const int lq = tid & 3;
    const float* Ap = A + (size_t)(m0 + lr) * lda + lq * 4;
    const float* Wp = W + (size_t)(n0 + lr) * ldw + lq * 4;
    const size_t astep = (size_t)64 * lda;
    const size_t wstep = (size_t)64 * ldw;

    float4 ar0 = *(const float4*)(Ap);
    float4 ar1 = *(const float4*)(Ap + astep);
    float4 br0 = *(const float4*)(Wp);
    float4 br1 = *(const float4*)(Wp + wstep);

    float acc[4][4][4];
#pragma unroll
    for (int i = 0; i < 4; i++)
#pragma unroll
        for (int j = 0; j < 4; j++)
#pragma unroll
            for (int q = 0; q < 4; q++) acc[i][j][q] = 0.f;

    const int nkt = K >> 4;
    for (int kt = 0; kt < nkt; kt++) {
        __syncthreads();
        sts_cvt4(&As[lr * 20 + lq * 4], ar0);
        sts_cvt4(&As[(lr + 64) * 20 + lq * 4], ar1);
        sts_cvt4(&Bs[lr * 20 + lq * 4], br0);
        sts_cvt4(&Bs[(lr + 64) * 20 + lq * 4], br1);
        __syncthreads();
        if (kt + 1 < nkt) {
            const float* Ap2 = Ap + (kt + 1) * 16;
            const float* Wp2 = Wp + (kt + 1) * 16;
            ar0 = *(const float4*)(Ap2);
            ar1 = *(const float4*)(Ap2 + astep);
            br0 = *(const float4*)(Wp2);
            br1 = *(const float4*)(Wp2 + wstep);
        }
#pragma unroll
        for (int kk = 0; kk < 16; kk += 8) {
            uint32_t af[4][4];
            uint32_t bf[4][2];
#pragma unroll
            for (int mt = 0; mt < 4; mt++) {
                int mr = wm + mt * 16 + g;
                af[mt][0] = __float_as_uint(As[mr * 20 + kk + c]);
                af[mt][1] = __float_as_uint(As[(mr + 8) * 20 + kk + c]);
                af[mt][2] = __float_as_uint(As[mr * 20 + kk + c + 4]);
                af[mt][3] = __float_as_uint(As[(mr + 8) * 20 + kk + c + 4]);
            }
#pragma unroll
            for (int nt = 0; nt < 4; nt++) {
                int nr = wn + nt * 8 + g;
                bf[nt][0] = __float_as_uint(Bs[nr * 20 + kk + c]);
                bf[nt][1] = __float_as_uint(Bs[nr * 20 + kk + c + 4]);
            }
#pragma unroll
            for (int mt = 0; mt < 4; mt++)
#pragma unroll
                for (int nt = 0; nt < 4; nt++)
                    mma_tf32(acc[mt][nt], af[mt], bf[nt]);
        }
    }

    float bv0[4], bv1[4];
#pragma unroll
    for (int nt = 0; nt < 4; nt++) {
        int col = n0 + wn + nt * 8 + 2 * c;
        float x0 = bias1 ? __ldg(&bias1[col]) : 0.f;
        float x1 = bias1 ? __ldg(&bias1[col + 1]) : 0.f;
        if (bias2) { x0 += __ldg(&bias2[col]); x1 += __ldg(&bias2[col + 1]); }
        bv0[nt] = x0; bv1[nt] = x1;
    }
#pragma unroll
    for (int mt = 0; mt < 4; mt++) {
        int r0 = m0 + wm + mt * 16 + g;
#pragma unroll
        for (int nt = 0; nt < 4; nt++) {
            int col = n0 + wn + nt * 8 + 2 * c;
            float2 o0 = make_float2(acc[mt][nt][0] + bv0[nt], acc[mt][nt][1] + bv1[nt]);
            float2 o1 = make_float2(acc[mt][nt][2] + bv0[nt], acc[mt][nt][3] + bv1[nt]);
            *(float2*)&C[(size_t)r0 * ldc + col] = o0;
            *(float2*)&C[(size_t)(r0 + 8) * ldc + col] = o1;
        }
    }
}

// ---------------- fused 2-layer pipelined persistent LSTM ----------------------
__global__ __launch_bounds__(LSTM_THREADS, 2) void k_lstm2(
    const float* __restrict__ gates0,     // [B*T, 2048] layer0 input gates (w/ biases)
    const float* __restrict__ Whh0,
    const float* __restrict__ Wih1,
    const float* __restrict__ Whh1,
    const float* __restrict__ bih1, const float* __restrict__ bhh1,
    const float* __restrict__ h_init_t,   // [512][16]
    float* __restrict__ ycat,             // y2 -> g_cat [b][t][1024]
    float* __restrict__ hn, float* __restrict__ cn,  // [2,B,H]
    float* __restrict__ h0a, float* __restrict__ h0b,
    float* __restrict__ h1a, float* __restrict__ h1b,
    float* __restrict__ y1a, float* __restrict__ y1b) {
    extern __shared__ float smf[];
    float* hs = smf;                         // [512*16] tf32 bits
    float* xs = smf + 512 * 16;              // [512*16] tf32 bits (layer1 only)
    float (*pr)[16][17] = (float(*)[16][17])(smf + 2 * 512 * 16);
    float* gsm = smf + 2 * 512 * 16 + 8 * 16 * 17;

    const int tid = threadIdx.x;
    const int layer = blockIdx.x >> 7;
    const int bidx = blockIdx.x & 127;
    const int w = tid >> 5, lane = tid & 31;
    const int g = lane >> 2, c = lane & 3;
    const uint32_t* hsu = (const uint32_t*)hs;
    const uint32_t* xsu = (const uint32_t*)xs;

    // ---- A fragments ----
    uint32_t afr_h[8][4];
    uint32_t afr_x[8][4];
    {
        const float* Wh_ = layer ? Whh1 : Whh0;
        int ng0 = (g >> 2) * 512 + bidx * 4 + (g & 3);
        int ng1 = ((g + 8) >> 2) * 512 + bidx * 4 + (g & 3);
        const float* w0 = Wh_ + (size_t)ng0 * 512;
        const float* w1 = Wh_ + (size_t)ng1 * 512;
#pragma unroll
        for (int kc = 0; kc < 8; kc++) {
            int kb = w * 64 + kc * 8;
            afr_h[kc][0] = f2tf32(__ldg(w0 + kb + c));
            afr_h[kc][1] = f2tf32(__ldg(w1 + kb + c));
            afr_h[kc][2] = f2tf32(__ldg(w0 + kb + c + 4));
            afr_h[kc][3] = f2tf32(__ldg(w1 + kb + c + 4));
        }
        if (layer) {
            const float* x0 = Wih1 + (size_t)ng0 * 512;
            const float* x1 = Wih1 + (size_t)ng1 * 512;
#pragma unroll
            for (int kc = 0; kc < 8; kc++) {
                int kb = w * 64 + kc * 8;
                afr_x[kc][0] = f2tf32(__ldg(x0 + kb + c));
                afr_x[kc][1] = f2tf32(__ldg(x1 + kb + c));
                afr_x[kc][2] = f2tf32(__ldg(x0 + kb + c + 4));
                afr_x[kc][3] = f2tf32(__ldg(x1 + kb + c + 4));
            }
        }
    }

    // reduce-thread identity + per-layer gate base
    const int r_nl = tid >> 4, r_b = tid & 15;
    const int r_ng = (r_nl >> 2) * 512 + bidx * 4 + (r_nl & 3);
    float gpre;
    if (layer) gpre = __ldg(&bih1[r_ng]) + __ldg(&bhh1[r_ng]);
    else       gpre = gates0[((size_t)(r_b * T_)) * 2048 + r_ng];

    // cell-update identity (tid < 64)
    float c_reg = 0.f;
    const int cb = tid & 15, chl = (tid >> 4) & 3;
    const int kh = bidx * 4 + chl;

    grid_barrier();

    for (int s = 0; s <= T_; s++) {
        const int t = layer ? (s - 1) : s;
        const bool active = layer ? (s >= 1) : (s < T_);
        if (active) {
            const float* hin;
            float* hout;
            if (layer == 0) {
                hin  = (t == 0) ? h_init_t : ((t & 1) ? h0a : h0b);
                hout = (t & 1) ? h0b : h0a;
            } else {
                hin  = (t == 0) ? h_init_t : ((t & 1) ? h1a : h1b);
                hout = (t & 1) ? h1b : h1a;
            }
            const float* xin = (t & 1) ? y1b : y1a;
            float* yout = (t & 1) ? y1b : y1a;

#pragma unroll
            for (int i = 0; i < 8; i++) {
                int idx = tid + 256 * i;
                float4 vh = __ldcg(((const float4*)hin) + idx);
                sts_cvt4(&hs[idx * 4], vh);
            }
            if (layer) {
#pragma unroll
                for (int i = 0; i < 8; i++) {
                    int idx = tid + 256 * i;
                    float4 vx = __ldcg(((const float4*)xin) + idx);
                    sts_cvt4(&xs[idx * 4], vx);
                }
            }
            __syncthreads();

            float acc0[4] = {0.f, 0.f, 0.f, 0.f};
            float acc1[4] = {0.f, 0.f, 0.f, 0.f};
#pragma unroll
            for (int kc = 0; kc < 8; kc++) {
                int kb = w * 64 + kc * 8;
                uint32_t b0[2], b1[2];
                b0[0] = hsu[(kb + c) * 16 + g];
                b0[1] = hsu[(kb + c + 4) * 16 + g];
                b1[0] = hsu[(kb + c) * 16 + 8 + g];
                b1[1] = hsu[(kb + c + 4) * 16 + 8 + g];
                mma_tf32(acc0, afr_h[kc], b0);
                mma_tf32(acc1, afr_h[kc], b1);
            }
            if (layer) {
#pragma unroll
                for (int kc = 0; kc < 8; kc++) {
                    int kb = w * 64 + kc * 8;
                    uint32_t b0[2], b1[2];
                    b0[0] = xsu[(kb + c) * 16 + g];
                    b0[1] = xsu[(kb + c + 4) * 16 + g];
                    b1[0] = xsu[(kb + c) * 16 + 8 + g];
                    b1[1] = xsu[(kb + c + 4) * 16 + 8 + g];
                    mma_tf32(acc0, afr_x[kc], b0);
                    mma_tf32(acc1, afr_x[kc], b1);
                }
            }
            pr[w][g][2 * c]         = acc0[0];
            pr[w][g][2 * c + 1]     = acc0[1];
            pr[w][g + 8][2 * c]     = acc0[2];
            pr[w][g + 8][2 * c + 1] = acc0[3];
            pr[w][g][8 + 2 * c]         = acc1[0];
            pr[w][g][8 + 2 * c + 1]     = acc1[1];
            pr[w][g + 8][8 + 2 * c]     = acc1[2];
            pr[w][g + 8][8 + 2 * c + 1] = acc1[3];
            __syncthreads();

            {
                float sum = gpre;
#pragma unroll
                for (int q = 0; q < 8; q++) sum += pr[q][r_nl][r_b];
                gsm[r_nl * 16 + r_b] = sum;
                if (layer == 0 && t + 1 < T_)
                    gpre = gates0[((size_t)(r_b * T_ + t + 1)) * 2048 + r_ng];
            }
            __syncthreads();

            if (tid < 64) {
                float gi = gsm[(0 * 4 + chl) * 16 + cb];
                float gf = gsm[(1 * 4 + chl) * 16 + cb];
                float gg = gsm[(2 * 4 + chl) * 16 + cb];
                float go = gsm[(3 * 4 + chl) * 16 + cb];
                float iv = fsig(gi);
                float fv = fsig(gf);
                float gv = ftanh(gg);
                float ov = fsig(go);
                c_reg = fv * c_reg + iv * gv;
                float hv = ov * ftanh(c_reg);
                hout[kh * 16 + cb] = hv;
                if (layer == 0) {
                    yout[kh * 16 + cb] = hv;
                    if (t == T_ - 1) {
                        hn[cb * 512 + kh] = hv;
                        cn[cb * 512 + kh] = c_reg;
                    }
                } else {
                    ycat[((size_t)(cb * T_ + t)) * 1024 + kh] = hv;
                    if (t == T_ - 1) {
                        hn[B_ * H_ + cb * 512 + kh] = hv;
                        cn[B_ * H_ + cb * 512 + kh] = c_reg;
                    }
                }
            }
        }
        grid_barrier();
    }
}

// ---------------- fused attention: energy + softmax + context -----------------
__global__ __launch_bounds__(256) void k_attn(
    const float* __restrict__ encf, const float* __restrict__ decf,
    const float* __restrict__ mem, const unsigned char* __restrict__ mask,
    const float* __restrict__ v, const float* __restrict__ vb,
    float* __restrict__ outcat) {
    __shared__ float df[8][512];
    __shared__ float vsh[512];
    __shared__ float row[512];
    __shared__ float en[8][128];
    const int b = blockIdx.x;
    const int t0 = blockIdx.y * 8;
    const int tid = threadIdx.x;
    const int w = tid >> 5, lane = tid & 31;

    for (int i = tid; i < 512; i += 256) vsh[i] = v[i];
    for (int i = tid; i < 8 * 512; i += 256) {
        int jj = i >> 9, h = i & 511;
        df[jj][h] = decf[((size_t)(b * T_ + t0 + jj)) * 512 + h];
    }
    __syncthreads();
    const float vbv = vb[0];

    for (int s = 0; s < S_; s++) {
        for (int i = tid; i < 512; i += 256) row[i] = encf[((size_t)(b * S_ + s)) * 512 + i];
        __syncthreads();
        float e = 0.f;
#pragma unroll
        for (int i = 0; i < 16; i++) {
            int h = lane + 32 * i;
            e = fmaf(vsh[h], ftanh(row[h] + df[w][h]), e);
        }
#pragma unroll
        for (int off = 16; off; off >>= 1) e += __shfl_xor_sync(0xffffffffu, e, off);
        if (lane == 0) {
            e += vbv;
            if (mask[b * S_ + s]) e = -1e9f;
            en[w][s] = e;
        }
        __syncthreads();
    }

    {
        float vals[4];
        float m = -1e30f;
#pragma unroll
        for (int i = 0; i < 4; i++) { vals[i] = en[w][lane + 32 * i]; m = fmaxf(m, vals[i]); }
#pragma unroll
        for (int off = 16; off; off >>= 1) m = fmaxf(m, __shfl_xor_sync(0xffffffffu, m, off));
        float ssum = 0.f;
#pragma unroll
        for (int i = 0; i < 4; i++) { vals[i] = __expf(vals[i] - m); ssum += vals[i]; }
#pragma unroll
        for (int off = 16; off; off >>= 1) ssum += __shfl_xor_sync(0xffffffffu, ssum, off);
        float inv = 1.f / ssum;
#pragma unroll
        for (int i = 0; i < 4; i++) en[w][lane + 32 * i] = vals[i] * inv;
    }
    __syncthreads();

    float c0[8], c1[8];
#pragma unroll
    for (int jj = 0; jj < 8; jj++) { c0[jj] = 0.f; c1[jj] = 0.f; }
    for (int s = 0; s < S_; s++) {
        for (int i = tid; i < 512; i += 256) row[i] = mem[((size_t)(b * S_ + s)) * 512 + i];
        __syncthreads();
        float m0 = row[tid], m1 = row[tid + 256];
#pragma unroll
        for (int jj = 0; jj < 8; jj++) {
            float a = en[jj][s];
            c0[jj] = fmaf(a, m0, c0[jj]);
            c1[jj] = fmaf(a, m1, c1[jj]);
        }
        __syncthreads();
    }
#pragma unroll
    for (int jj = 0; jj < 8; jj++) {
        size_t rr = ((size_t)(b * T_ + t0 + jj)) * 1024 + 512;
        outcat[rr + tid] = c0[jj];
        outcat[rr + tid + 256] = c1[jj];
    }
}

// ---------------- launch -------------------------------------------------------
extern "C" void kernel_launch(void* const* d_in, const int* in_sizes, int n_in,
                              void* d_out, int out_size) {
    (void)in_sizes; (void)n_in; (void)out_size;
    const int*   tgt  = (const int*)d_in[0];
    const float* mem  = (const float*)d_in[1];
    const unsigned char* mask = (const unsigned char*)d_in[2];
    const float* emb  = (const float*)d_in[3];
    const float* Wih0 = (const float*)d_in[4];
    const float* Whh0 = (const float*)d_in[5];
    const float* bih0 = (const float*)d_in[6];
    const float* bhh0 = (const float*)d_in[7];
    const float* Wih1 = (const float*)d_in[8];
    const float* Whh1 = (const float*)d_in[9];
    const float* bih1 = (const float*)d_in[10];
    const float* bhh1 = (const float*)d_in[11];
    const float* Wh   = (const float*)d_in[12];
    const float* bh   = (const float*)d_in[13];
    const float* Ws   = (const float*)d_in[14];
    const float* bs   = (const float*)d_in[15];
    const float* v    = (const float*)d_in[16];
    const float* vb   = (const float*)d_in[17];
    const float* Wout = (const float*)d_in[18];
    const float* bout = (const float*)d_in[19];

    float* out = (float*)d_out;
    float* logits = out;
    float* hn = out + (size_t)B_ * T_ * V_;
    float* cn = hn + 2 * B_ * H_;

    float *px, *pgates, *pcat, *pencf, *pdecf, *pench;
    float *ph0a, *ph0b, *ph1a, *ph1b, *py1a, *py1b;
    cudaGetSymbolAddress((void**)&px, g_x);
    cudaGetSymbolAddress((void**)&pgates, g_gates);
    cudaGetSymbolAddress((void**)&pcat, g_cat);
    cudaGetSymbolAddress((void**)&pencf, g_encf);
    cudaGetSymbolAddress((void**)&pdecf, g_decf);
    cudaGetSymbolAddress((void**)&pench, g_ench_t);
    cudaGetSymbolAddress((void**)&ph0a, g_h0a);
    cudaGetSymbolAddress((void**)&ph0b, g_h0b);
    cudaGetSymbolAddress((void**)&ph1a, g_h1a);
    cudaGetSymbolAddress((void**)&ph1b, g_h1b);
    cudaGetSymbolAddress((void**)&py1a, g_y1a);
    cudaGetSymbolAddress((void**)&py1b, g_y1b);

    cudaFuncSetAttribute(k_lstm2, cudaFuncAttributeMaxDynamicSharedMemorySize, LSTM_SMEM);

    // 1. embedding + enc_hidden (transposed)
    k_embed<<<2048, 128>>>(tgt, emb, px);
    k_mean<<<B_, 512>>>(mem, pench);

    // 2. attention enc features (independent of LSTM)
    gemm_tf32<<<dim3(4, 16), 256>>>(mem, 512, Wh, 512, 512, bh, nullptr, pencf, 512);

    // 3. layer0 input gates (tf32 mma)
    gemm_tf32<<<dim3(16, 16), 256>>>(px, 512, Wih0, 512, 512, bih0, bhh0, pgates, 2048);

    // 4. fused pipelined 2-layer LSTM (y2 -> first half of g_cat)
    k_lstm2<<<TOT_CTAS, LSTM_THREADS, LSTM_SMEM>>>(
        pgates, Whh0, Wih1, Whh1, bih1, bhh1, pench,
        pcat, hn, cn, ph0a, ph0b, ph1a, ph1b, py1a, py1b);

    // 5. dec features
    gemm_tf32<<<dim3(4, 16), 256>>>(pcat, 1024, Ws, 512, 512, bs, nullptr, pdecf, 512);

    // 6. fused energy/softmax/context -> second half of g_cat
    k_attn<<<dim3(B_, T_ / 8), 256>>>(pencf, pdecf, mem, mask, v, vb, pcat);

    // 7. output projection (tf32 mma)
    gemm_tf32<<<dim3(32, 16), 256>>>(pcat, 1024, Wout, 1024, 1024, bout, nullptr, logits, 4096);
}